// round 7
// baseline (speedup 1.0000x reference)
#include <cuda_runtime.h>
#include <cstdint>

// DConv implicit GEMM, mma.sync tf32 (legacy TC path; tcgen05 blocked by
// compute_103 virtual arch in the harness build).
//
// Per (b, y):  D[o][x] = sum_k W[o][k] * B[k][x],  K = 576, k = c*9 + ky*3 + kx
//   B[k][x] = xz[c][y-1+ky-dy_c][x+kx-1-dx_c]   (zero outside [0,160)^2)
//   (dx,dy) from c%5: 0:(0,0) 1:(1,0) 2:(0,1) 3:(-1,0) 4:(0,-1)
//
// R6 = R4 (450us) structure: 72-row K chunks x 8, double buffer, 1 CTA/SM,
// regs unconstrained; ONLY changes: warp grid 4Mx2N -> 2Mx4N (B LDS re-reads
// halved) and c-major K (direct weight gather, no woff table).

#define HH 160
#define WW 160
#define CIN 64
#define COUT 64
#define THREADS 256
#define NCHUNK 8
#define KCH 72                         // K rows per chunk (9 k-steps of 8)

#define DESC_OFF 0                     // 576 x int2 = 4608 B
#define BUF_OFF  4608
#define A_BYTES  18432                 // 4 mblk x 9 ks x 32 lane x 16B
#define B_BYTES  46080                 // 20 nfrag x 9 ks x 32 lane x 8B
#define BUF_STRIDE (A_BYTES + B_BYTES)         // 64512
#define SMEM_TOTAL (BUF_OFF + 2 * BUF_STRIDE)  // 133632

__device__ __forceinline__ uint32_t f2tf(float f) {
    uint32_t r;
    asm("cvt.rna.tf32.f32 %0, %1;" : "=r"(r) : "f"(f));
    return r;
}

__device__ __forceinline__ void mma_tf32(float* c, uint4 a, uint2 b) {
    asm volatile(
        "mma.sync.aligned.m16n8k8.row.col.f32.tf32.tf32.f32 "
        "{%0,%1,%2,%3}, {%4,%5,%6,%7}, {%8,%9}, {%0,%1,%2,%3};"
        : "+f"(c[0]), "+f"(c[1]), "+f"(c[2]), "+f"(c[3])
        : "r"(a.x), "r"(a.y), "r"(a.z), "r"(a.w), "r"(b.x), "r"(b.y));
}

extern __shared__ char smem[];

__global__ __launch_bounds__(THREADS, 1)
void dconv_mma_kernel(const float* __restrict__ x,
                      const float* __restrict__ w,
                      float* __restrict__ out)
{
    const int y    = blockIdx.x;
    const int b    = blockIdx.y;
    const int tid  = threadIdx.x;
    const int lane = tid & 31;
    const int wid  = tid >> 5;
    const int g  = lane >> 2;          // groupID (row / pixel within frag)
    const int t  = lane & 3;           // thread-in-group
    const int fm = wid & 1;            // M-warp: o block of 32
    const int wn = wid >> 1;           // N-warp: x block of 40

    int2* desc = (int2*)(smem + DESC_OFF);

    // ---- prologue: per-K-row gather descriptors (CTA-uniform) ----
    for (int k = tid; k < 576; k += THREADS) {
        int c  = k / 9;
        int t9 = k - c * 9;
        int ky = t9 / 3;
        int kx = t9 - ky * 3;
        int m5 = c % 5;
        int dy = (m5 == 2) ? 1 : ((m5 == 4) ? -1 : 0);
        int dx = (m5 == 1) ? 1 : ((m5 == 3) ? -1 : 0);
        int gy  = y - 1 + ky - dy;
        int off = kx - 1 - dx;                           // in [-2, 2]
        int rowBase = (c * (HH * WW) + gy * WW + off) * 4;  // bytes
        int flags = (((unsigned)gy < (unsigned)HH) ? 256 : 0) | (off + 2);
        desc[k] = make_int2(rowBase, flags);
    }
    __syncthreads();

    const char* xbp = (const char*)(x + (size_t)b * CIN * HH * WW);

    float acc[2][5][4];
    #pragma unroll
    for (int mf = 0; mf < 2; ++mf)
        #pragma unroll
        for (int fn = 0; fn < 5; ++fn)
            #pragma unroll
            for (int i = 0; i < 4; ++i) acc[mf][fn][i] = 0.f;

    const int qBase = tid >> 5;        // A staging: q = qBase + i*8

    for (int ch = 0; ch < NCHUNK; ++ch) {
        char* bufA = smem + BUF_OFF + (ch & 1) * BUF_STRIDE;
        char* bufB = bufA + A_BYTES;
        const int kBase = ch * KCH;
        const int2* dch = desc + kBase;

        // ---- stage A (weights): 1152 slots x 16B, ceil(1152/256)=5/thread ----
        #pragma unroll
        for (int i = 0; i < 5; ++i) {
            int s = tid + i * THREADS;
            if (s < 1152) {
                int q   = s >> 5;                // (mblk, ks), q < 36
                int mbk = q / 9;
                int ks  = q - mbk * 9;
                int m0  = mbk * 16 + g;
                int k0  = kBase + ks * 8 + t;
                const float* w0 = w + m0 * 576 + k0;
                const float* w1 = w0 + 8 * 576;
                uint4 v = make_uint4(f2tf(w0[0]), f2tf(w1[0]),
                                     f2tf(w0[4]), f2tf(w1[4]));
                *(uint4*)(bufA + s * 16) = v;
            }
        }

        // ---- stage B (shifted input gather): 180 pairs, 23/warp w/ guard ----
        #pragma unroll
        for (int i = 0; i < 23; ++i) {
            int p = wid + i * 8;                 // fnG*9 + ks, p < 180
            if (p < 180) {
                int fnG = p / 9;
                int x0  = fnG * 8 + g;           // pixel
                int kl  = (p - fnG * 9) * 8 + t; // k within chunk
                int2 d0 = dch[kl];
                int2 d1 = dch[kl + 4];
                int gx0 = x0 + (d0.y & 255) - 2;
                int gx1 = x0 + (d1.y & 255) - 2;
                bool p0 = (d0.y & 256) && (unsigned)gx0 < (unsigned)WW;
                bool p1 = (d1.y & 256) && (unsigned)gx1 < (unsigned)WW;
                float v0 = p0 ? *(const float*)(xbp + d0.x + x0 * 4) : 0.f;
                float v1 = p1 ? *(const float*)(xbp + d1.x + x0 * 4) : 0.f;
                *(uint2*)(bufB + p * 256 + lane * 8) = make_uint2(f2tf(v0), f2tf(v1));
            }
        }

        __syncthreads();

        // ---- compute: 9 k-steps x (2 m-frags x 5 n-frags) ----
        #pragma unroll
        for (int ks = 0; ks < 9; ++ks) {
            uint4 a0 = *(const uint4*)(bufA + (((fm * 2 + 0) * 9 + ks) * 32 + lane) * 16);
            uint4 a1 = *(const uint4*)(bufA + (((fm * 2 + 1) * 9 + ks) * 32 + lane) * 16);
            #pragma unroll
            for (int fn = 0; fn < 5; ++fn) {
                uint2 bb = *(const uint2*)(bufB +
                              (((wn * 5 + fn) * 9 + ks) * 32 + lane) * 8);
                mma_tf32(acc[0][fn], a0, bb);
                mma_tf32(acc[1][fn], a1, bb);
            }
        }
        // double-buffered: the sync above separates this chunk's compute from
        // next chunk's staging of the other buffer.
    }

    // ---- epilogue: D[m][x] -> out[b][m][y][x] ----
    #pragma unroll
    for (int mf = 0; mf < 2; ++mf) {
        int m0 = fm * 32 + mf * 16 + g;
        #pragma unroll
        for (int fn = 0; fn < 5; ++fn) {
            int xg = wn * 40 + fn * 8 + t * 2;
            float* o0 = out + (((size_t)b * COUT + m0) * HH + y) * WW + xg;
            float* o1 = o0 + 8 * HH * WW;
            *(float2*)o0 = make_float2(acc[mf][fn][0], acc[mf][fn][1]);
            *(float2*)o1 = make_float2(acc[mf][fn][2], acc[mf][fn][3]);
        }
    }
}

extern "C" void kernel_launch(void* const* d_in, const int* in_sizes, int n_in,
                              void* d_out, int out_size)
{
    const float* x = (const float*)d_in[0];
    const float* w = (const float*)d_in[1];
    float* out = (float*)d_out;

    cudaFuncSetAttribute(dconv_mma_kernel,
                         cudaFuncAttributeMaxDynamicSharedMemorySize, SMEM_TOTAL);

    dim3 grid(HH, 16);
    dconv_mma_kernel<<<grid, THREADS, SMEM_TOTAL>>>(x, w, out);
}

// round 9
// speedup vs baseline: 2.9925x; 2.9925x over previous
#include <cuda_runtime.h>
#include <cstdint>

// DConv implicit GEMM, mma.sync tf32 (legacy TC path; tcgen05 blocked by
// compute_103 virtual arch in the harness build).
//
// Per (b, y):  D[o][x] = sum_k W[o][k] * B[k][x],  K = 576, k = c*9 + ky*3 + kx
//   B[k][x] = xz[c][y-1+ky-dy_c][x+kx-1-dx_c]   (zero outside [0,160)^2)
//   (dx,dy) from c%5: 0:(0,0) 1:(1,0) 2:(0,1) 3:(-1,0) 4:(0,-1)
//
// R7: 2Mx4N warp grid + c-major K (from R6) with R4's two-phase staging
// (batch ALL chunk LDGs into register arrays, then cvt+STS) restoring the
// memory-level parallelism that made R4 fast. 72-row chunks x 8, double
// buffered, 1 CTA/SM, registers unconstrained.

#define HH 160
#define WW 160
#define CIN 64
#define COUT 64
#define THREADS 256
#define NCHUNK 8
#define KCH 72                         // K rows per chunk (9 k-steps of 8)

#define DESC_OFF 0                     // 576 x int2 = 4608 B
#define BUF_OFF  4608
#define A_BYTES  18432                 // 4 mblk x 9 ks x 32 lane x 16B
#define B_BYTES  46080                 // 20 nfrag x 9 ks x 32 lane x 8B
#define BUF_STRIDE (A_BYTES + B_BYTES)         // 64512
#define SMEM_TOTAL (BUF_OFF + 2 * BUF_STRIDE)  // 133632

__device__ __forceinline__ uint32_t f2tf(float f) {
    uint32_t r;
    asm("cvt.rna.tf32.f32 %0, %1;" : "=r"(r) : "f"(f));
    return r;
}

__device__ __forceinline__ void mma_tf32(float* c, uint4 a, uint2 b) {
    asm volatile(
        "mma.sync.aligned.m16n8k8.row.col.f32.tf32.tf32.f32 "
        "{%0,%1,%2,%3}, {%4,%5,%6,%7}, {%8,%9}, {%0,%1,%2,%3};"
        : "+f"(c[0]), "+f"(c[1]), "+f"(c[2]), "+f"(c[3])
        : "r"(a.x), "r"(a.y), "r"(a.z), "r"(a.w), "r"(b.x), "r"(b.y));
}

extern __shared__ char smem[];

__global__ __launch_bounds__(THREADS, 1)
void dconv_mma_kernel(const float* __restrict__ x,
                      const float* __restrict__ w,
                      float* __restrict__ out)
{
    const int y    = blockIdx.x;
    const int b    = blockIdx.y;
    const int tid  = threadIdx.x;
    const int lane = tid & 31;
    const int wid  = tid >> 5;
    const int g  = lane >> 2;          // groupID (row / pixel within frag)
    const int t  = lane & 3;           // thread-in-group
    const int fm = wid & 1;            // M-warp: o block of 32
    const int wn = wid >> 1;           // N-warp: x block of 40

    int2* desc = (int2*)(smem + DESC_OFF);

    // ---- prologue: per-K-row gather descriptors (CTA-uniform) ----
    for (int k = tid; k < 576; k += THREADS) {
        int c  = k / 9;
        int t9 = k - c * 9;
        int ky = t9 / 3;
        int kx = t9 - ky * 3;
        int m5 = c % 5;
        int dy = (m5 == 2) ? 1 : ((m5 == 4) ? -1 : 0);
        int dx = (m5 == 1) ? 1 : ((m5 == 3) ? -1 : 0);
        int gy  = y - 1 + ky - dy;
        int off = kx - 1 - dx;                           // in [-2, 2]
        int rowBase = (c * (HH * WW) + gy * WW + off) * 4;  // bytes
        int flags = (((unsigned)gy < (unsigned)HH) ? 256 : 0) | (off + 2);
        desc[k] = make_int2(rowBase, flags);
    }
    __syncthreads();

    const char* xbp = (const char*)(x + (size_t)b * CIN * HH * WW);

    float acc[2][5][4];
    #pragma unroll
    for (int mf = 0; mf < 2; ++mf)
        #pragma unroll
        for (int fn = 0; fn < 5; ++fn)
            #pragma unroll
            for (int i = 0; i < 4; ++i) acc[mf][fn][i] = 0.f;

    for (int ch = 0; ch < NCHUNK; ++ch) {
        char* bufA = smem + BUF_OFF + (ch & 1) * BUF_STRIDE;
        char* bufB = bufA + A_BYTES;
        const int kBase = ch * KCH;
        const int2* dch = desc + kBase;

        // ======== PHASE 1: batch all global loads into registers ========

        // A (weights): 1152 slots x 16B -> 5 slots/thread (guarded)
        float av[5][4];
        int   sA[5];
        #pragma unroll
        for (int i = 0; i < 5; ++i) {
            int s = tid + i * THREADS;
            sA[i] = s;
            if (s < 1152) {
                int q   = s >> 5;                // (mblk, ks), q < 36
                int mbk = q / 9;
                int ks  = q - mbk * 9;
                int m0  = mbk * 16 + g;
                int k0  = kBase + ks * 8 + t;
                const float* w0 = w + m0 * 576 + k0;
                const float* w1 = w0 + 8 * 576;
                av[i][0] = w0[0];
                av[i][1] = w1[0];
                av[i][2] = w0[4];
                av[i][3] = w1[4];
            }
        }

        // B (shifted input gather): 180 pairs -> 23/warp (guarded)
        float bv[23][2];
        #pragma unroll
        for (int i = 0; i < 23; ++i) {
            int p = wid + i * 8;                 // fnG*9 + ks, p < 180
            bool ok = p < 180;
            int fnG = p / 9;
            int x0  = fnG * 8 + g;               // pixel
            int kl  = (p - fnG * 9) * 8 + t;     // k within chunk
            int2 d0 = ok ? dch[kl]     : make_int2(0, 0);
            int2 d1 = ok ? dch[kl + 4] : make_int2(0, 0);
            int gx0 = x0 + (d0.y & 255) - 2;
            int gx1 = x0 + (d1.y & 255) - 2;
            bool p0 = ok && (d0.y & 256) && (unsigned)gx0 < (unsigned)WW;
            bool p1 = ok && (d1.y & 256) && (unsigned)gx1 < (unsigned)WW;
            bv[i][0] = p0 ? *(const float*)(xbp + d0.x + x0 * 4) : 0.f;
            bv[i][1] = p1 ? *(const float*)(xbp + d1.x + x0 * 4) : 0.f;
        }

        // ======== PHASE 2: cvt + STS commit ========
        #pragma unroll
        for (int i = 0; i < 5; ++i) {
            if (sA[i] < 1152) {
                uint4 v = make_uint4(f2tf(av[i][0]), f2tf(av[i][1]),
                                     f2tf(av[i][2]), f2tf(av[i][3]));
                *(uint4*)(bufA + sA[i] * 16) = v;
            }
        }
        #pragma unroll
        for (int i = 0; i < 23; ++i) {
            int p = wid + i * 8;
            if (p < 180) {
                uint2 v = make_uint2(f2tf(bv[i][0]), f2tf(bv[i][1]));
                *(uint2*)(bufB + p * 256 + lane * 8) = v;
            }
        }

        __syncthreads();

        // ---- compute: 9 k-steps x (2 m-frags x 5 n-frags) ----
        #pragma unroll
        for (int ks = 0; ks < 9; ++ks) {
            uint4 a0 = *(const uint4*)(bufA + (((fm * 2 + 0) * 9 + ks) * 32 + lane) * 16);
            uint4 a1 = *(const uint4*)(bufA + (((fm * 2 + 1) * 9 + ks) * 32 + lane) * 16);
            #pragma unroll
            for (int fn = 0; fn < 5; ++fn) {
                uint2 bb = *(const uint2*)(bufB +
                              (((wn * 5 + fn) * 9 + ks) * 32 + lane) * 8);
                mma_tf32(acc[0][fn], a0, bb);
                mma_tf32(acc[1][fn], a1, bb);
            }
        }
        // double-buffered: the sync above separates this chunk's compute from
        // next chunk's staging of the other buffer.
    }

    // ---- epilogue: D[m][x] -> out[b][m][y][x] ----
    #pragma unroll
    for (int mf = 0; mf < 2; ++mf) {
        int m0 = fm * 32 + mf * 16 + g;
        #pragma unroll
        for (int fn = 0; fn < 5; ++fn) {
            int xg = wn * 40 + fn * 8 + t * 2;
            float* o0 = out + (((size_t)b * COUT + m0) * HH + y) * WW + xg;
            float* o1 = o0 + 8 * HH * WW;
            *(float2*)o0 = make_float2(acc[mf][fn][0], acc[mf][fn][1]);
            *(float2*)o1 = make_float2(acc[mf][fn][2], acc[mf][fn][3]);
        }
    }
}

extern "C" void kernel_launch(void* const* d_in, const int* in_sizes, int n_in,
                              void* d_out, int out_size)
{
    const float* x = (const float*)d_in[0];
    const float* w = (const float*)d_in[1];
    float* out = (float*)d_out;

    cudaFuncSetAttribute(dconv_mma_kernel,
                         cudaFuncAttributeMaxDynamicSharedMemorySize, SMEM_TOTAL);

    dim3 grid(HH, 16);
    dconv_mma_kernel<<<grid, THREADS, SMEM_TOTAL>>>(x, w, out);
}